// round 1
// baseline (speedup 1.0000x reference)
#include <cuda_runtime.h>
#include <cstdint>

#define BB 256
#define NN 512
#define EE 64
#define OO 64
#define KK 8
#define NSPLIT 4
#define NCHUNK (NN / NSPLIT)   // 128

// Scratch (static device allocations — allowed)
__device__ float g_priors[BB * NN * OO];            // 33.5 MB
__device__ float g_zpart[BB * NSPLIT * KK * OO];    // 2 MB
__device__ float g_vacc[BB * KK * OO];              // 0.5 MB

__device__ __forceinline__ float fast_ex2(float x) {
    float y; asm("ex2.approx.f32 %0, %1;" : "=f"(y) : "f"(x)); return y;
}
__device__ __forceinline__ float fast_rcp(float x) {
    float y; asm("rcp.approx.f32 %0, %1;" : "=f"(y) : "f"(x)); return y;
}

// ---------------------------------------------------------------------------
// priors[b,n,o] = sum_e emb[b,n,e] * S[e,o]
// One block = 64 rows (of B*N) x 64 cols. fp32, smem-tiled, 4x4 reg tile.
// ---------------------------------------------------------------------------
__global__ void __launch_bounds__(256) gemm_kernel(const float* __restrict__ emb,
                                                   const float* __restrict__ S) {
    __shared__ float sA[64][68];   // transposed: sA[e][row]
    __shared__ float sB[64][68];   // sB[e][col]
    const int t = threadIdx.x;
    const float* embBase = emb + (size_t)blockIdx.x * 64 * EE;

    #pragma unroll
    for (int i = t; i < 1024; i += 256) {
        int row = i >> 4;
        int e4  = (i & 15) << 2;
        float4 v = *(const float4*)(embBase + row * EE + e4);
        sA[e4 + 0][row] = v.x; sA[e4 + 1][row] = v.y;
        sA[e4 + 2][row] = v.z; sA[e4 + 3][row] = v.w;
    }
    #pragma unroll
    for (int i = t; i < 1024; i += 256) {
        int e  = i >> 4;
        int c4 = (i & 15) << 2;
        *(float4*)&sB[e][c4] = *(const float4*)(S + e * OO + c4);
    }
    __syncthreads();

    const int tr = (t >> 4) << 2;   // row base (0..60)
    const int tc = (t & 15) << 2;   // col base (0..60)
    float acc[4][4];
    #pragma unroll
    for (int i = 0; i < 4; i++)
        #pragma unroll
        for (int j = 0; j < 4; j++) acc[i][j] = 0.f;

    #pragma unroll 8
    for (int e = 0; e < 64; e++) {
        float4 a = *(const float4*)&sA[e][tr];
        float4 b = *(const float4*)&sB[e][tc];
        float av[4] = {a.x, a.y, a.z, a.w};
        float bv[4] = {b.x, b.y, b.z, b.w};
        #pragma unroll
        for (int i = 0; i < 4; i++)
            #pragma unroll
            for (int j = 0; j < 4; j++)
                acc[i][j] = fmaf(av[i], bv[j], acc[i][j]);
    }

    float* outBase = g_priors + (size_t)blockIdx.x * 64 * OO;
    #pragma unroll
    for (int i = 0; i < 4; i++) {
        float4 v = make_float4(acc[i][0], acc[i][1], acc[i][2], acc[i][3]);
        *(float4*)(outBase + (tr + i) * OO + tc) = v;
    }
}

// ---------------------------------------------------------------------------
// One routing iteration (split over N into NSPLIT chunks per b):
//   delta[n,k] = dot(priors[b,n,:], Vacc[b,k,:])        (skipped if FIRST)
//   w[k]       = softmax_k(cc0[b,k,n,o] + delta[n,k])
//   zpart[b,sp,k,o] = sum_{n in chunk} w[k] * priors[b,n,o]
// ---------------------------------------------------------------------------
template <bool FIRST>
__global__ void __launch_bounds__(256) route_kernel(const float* __restrict__ cc) {
    __shared__ float ps[NCHUNK][68];   // priors chunk (padded, reused for reduction)
    __shared__ float ds[NCHUNK][8];    // delta
    __shared__ float vs[KK][68];       // Vacc slice

    const int t  = threadIdx.x;
    const int b  = blockIdx.x >> 2;
    const int sp = blockIdx.x & 3;
    const int n0 = sp * NCHUNK;

    const float* pBase = g_priors + ((size_t)b * NN + n0) * OO;
    for (int i = t; i < NCHUNK * 16; i += 256) {
        int n  = i >> 4;
        int o4 = (i & 15) << 2;
        *(float4*)&ps[n][o4] = *(const float4*)(pBase + n * OO + o4);
    }
    if (!FIRST) {
        if (t < KK * 16) {
            int k  = t >> 4;
            int o4 = (t & 15) << 2;
            *(float4*)&vs[k][o4] = *(const float4*)(g_vacc + ((size_t)b * KK + k) * OO + o4);
        }
    }
    __syncthreads();

    if (!FIRST) {
        for (int id = t; id < NCHUNK * KK; id += 256) {
            int n = id >> 3;
            int k = id & 7;
            float s = 0.f;
            #pragma unroll
            for (int o = 0; o < OO; o++) s = fmaf(ps[n][o], vs[k][o], s);
            ds[n][k] = s;
        }
        __syncthreads();
    }

    const int og   = t & 15;        // o-group: 4 consecutive o's
    const int ob   = og << 2;
    const int nrep = t >> 4;        // 16 n-replicas
    float acc[KK][4];
    #pragma unroll
    for (int k = 0; k < KK; k++) {
        acc[k][0] = 0.f; acc[k][1] = 0.f; acc[k][2] = 0.f; acc[k][3] = 0.f;
    }

    const float* ccBase = cc + ((size_t)b * KK * NN + n0) * OO + ob;
    const float L2E = 1.4426950408889634f;

    for (int n = nrep; n < NCHUNK; n += 16) {
        float4 p4 = *(const float4*)&ps[n][ob];
        float pa[4] = {p4.x, p4.y, p4.z, p4.w};
        float c[KK][4];
        #pragma unroll
        for (int k = 0; k < KK; k++) {
            float4 c4 = *(const float4*)(ccBase + ((size_t)k * NN + n) * OO);
            c[k][0] = c4.x; c[k][1] = c4.y; c[k][2] = c4.z; c[k][3] = c4.w;
            if (!FIRST) {
                float d = ds[n][k];
                c[k][0] += d; c[k][1] += d; c[k][2] += d; c[k][3] += d;
            }
        }
        float m[4] = {c[0][0], c[0][1], c[0][2], c[0][3]};
        #pragma unroll
        for (int k = 1; k < KK; k++) {
            #pragma unroll
            for (int j = 0; j < 4; j++) m[j] = fmaxf(m[j], c[k][j]);
        }
        float ml[4];
        #pragma unroll
        for (int j = 0; j < 4; j++) ml[j] = m[j] * L2E;
        float s[4] = {0.f, 0.f, 0.f, 0.f};
        #pragma unroll
        for (int k = 0; k < KK; k++) {
            #pragma unroll
            for (int j = 0; j < 4; j++) {
                float e = fast_ex2(fmaf(c[k][j], L2E, -ml[j]));
                c[k][j] = e;
                s[j] += e;
            }
        }
        float pr[4];
        #pragma unroll
        for (int j = 0; j < 4; j++) pr[j] = pa[j] * fast_rcp(s[j]);
        #pragma unroll
        for (int k = 0; k < KK; k++) {
            #pragma unroll
            for (int j = 0; j < 4; j++)
                acc[k][j] = fmaf(c[k][j], pr[j], acc[k][j]);
        }
    }

    // Reduce 16 n-replicas: first pair-reduce within warp (lane ^ 16)...
    #pragma unroll
    for (int k = 0; k < KK; k++) {
        #pragma unroll
        for (int j = 0; j < 4; j++)
            acc[k][j] += __shfl_xor_sync(0xffffffffu, acc[k][j], 16);
    }
    __syncthreads();   // done reading ps — reuse as reduction buffer

    // ...then across the 8 warps via smem (stride 33 floats = conflict-free).
    float* red = &ps[0][0];   // needs 128*33 = 4224 floats (ps holds 8704)
    const int w    = t >> 5;
    const int lane = t & 31;
    if (lane < 16) {
        float* dst = red + (w * 16 + lane) * 33;
        #pragma unroll
        for (int k = 0; k < KK; k++) {
            #pragma unroll
            for (int j = 0; j < 4; j++) dst[k * 4 + j] = acc[k][j];
        }
    }
    __syncthreads();

    for (int id = t; id < 512; id += 256) {
        int og_ = id >> 5;
        int kj  = id & 31;
        float ssum = 0.f;
        #pragma unroll
        for (int w_ = 0; w_ < 8; w_++) ssum += red[(w_ * 16 + og_) * 33 + kj];
        int k = kj >> 2;
        int j = kj & 3;
        int o = (og_ << 2) + j;
        g_zpart[(((size_t)b * NSPLIT + sp) * KK + k) * OO + o] = ssum;
    }
}

// ---------------------------------------------------------------------------
// Sum partials over splits, squash. MODE 0: Vacc = v (iter 0);
// MODE 1: Vacc += v; MODE 2: write final output.
// One warp per (b,k); 2 o's per lane.
// ---------------------------------------------------------------------------
template <int MODE>
__global__ void __launch_bounds__(256) finish_kernel(float* __restrict__ out) {
    const int gw   = (blockIdx.x << 3) + (threadIdx.x >> 5);   // 0..2047
    const int lane = threadIdx.x & 31;
    const int b = gw >> 3;
    const int k = gw & 7;

    float z0 = 0.f, z1 = 0.f;
    #pragma unroll
    for (int sp = 0; sp < NSPLIT; sp++) {
        const float* zp = g_zpart + (((size_t)b * NSPLIT + sp) * KK + k) * OO;
        z0 += zp[lane];
        z1 += zp[lane + 32];
    }
    float sq = z0 * z0 + z1 * z1;
    #pragma unroll
    for (int off = 16; off; off >>= 1)
        sq += __shfl_xor_sync(0xffffffffu, sq, off);

    float scale = sq / ((1.f + sq) * sqrtf(sq + 1e-9f));
    float v0 = scale * z0;
    float v1 = scale * z1;

    size_t base = ((size_t)b * KK + k) * OO;
    if (MODE == 2) {
        out[base + lane]      = v0;
        out[base + lane + 32] = v1;
    } else if (MODE == 0) {
        g_vacc[base + lane]      = v0;
        g_vacc[base + lane + 32] = v1;
    } else {
        g_vacc[base + lane]      += v0;
        g_vacc[base + lane + 32] += v1;
    }
}

// ---------------------------------------------------------------------------
extern "C" void kernel_launch(void* const* d_in, const int* in_sizes, int n_in,
                              void* d_out, int out_size) {
    const float* emb = (const float*)d_in[0];   // (B, N, E)
    const float* S   = (const float*)d_in[1];   // (E, O)
    const float* cc  = (const float*)d_in[2];   // (B, K, N, O)
    float* out = (float*)d_out;                 // (B, K, O)
    (void)in_sizes; (void)n_in; (void)out_size;

    gemm_kernel<<<BB * NN / 64, 256>>>(emb, S);

    route_kernel<true><<<BB * NSPLIT, 256>>>(cc);
    finish_kernel<0><<<BB * KK / 8, 256>>>(nullptr);

    route_kernel<false><<<BB * NSPLIT, 256>>>(cc);
    finish_kernel<1><<<BB * KK / 8, 256>>>(nullptr);

    route_kernel<false><<<BB * NSPLIT, 256>>>(cc);
    finish_kernel<2><<<BB * KK / 8, 256>>>(out);
}

// round 2
// speedup vs baseline: 1.1104x; 1.1104x over previous
#include <cuda_runtime.h>
#include <cstdint>

#define BB 256
#define NN 512
#define EE 64
#define OO 64
#define KK 8
#define NSPLIT 8
#define NCHUNK (NN / NSPLIT)   // 64

// Scratch (static device allocations — allowed)
__device__ float g_priors[BB * NN * OO];            // 33.5 MB
__device__ float g_zpart[BB * NSPLIT * KK * OO];    // 4 MB
__device__ float g_vacc[BB * KK * OO];              // 0.5 MB

__device__ __forceinline__ float fast_ex2(float x) {
    float y; asm("ex2.approx.f32 %0, %1;" : "=f"(y) : "f"(x)); return y;
}
__device__ __forceinline__ float fast_rcp(float x) {
    float y; asm("rcp.approx.f32 %0, %1;" : "=f"(y) : "f"(x)); return y;
}

// ---------------------------------------------------------------------------
// priors[b,n,o] = sum_e emb[b,n,e] * S[e,o]
// One block = 64 rows (of B*N) x 64 cols. fp32, smem-tiled, 4x4 reg tile.
// ---------------------------------------------------------------------------
__global__ void __launch_bounds__(256) gemm_kernel(const float* __restrict__ emb,
                                                   const float* __restrict__ S) {
    __shared__ float sA[64][68];   // transposed: sA[e][row]
    __shared__ float sB[64][68];   // sB[e][col]
    const int t = threadIdx.x;
    const float* embBase = emb + (size_t)blockIdx.x * 64 * EE;

    #pragma unroll
    for (int i = t; i < 1024; i += 256) {
        int row = i >> 4;
        int e4  = (i & 15) << 2;
        float4 v = *(const float4*)(embBase + row * EE + e4);
        sA[e4 + 0][row] = v.x; sA[e4 + 1][row] = v.y;
        sA[e4 + 2][row] = v.z; sA[e4 + 3][row] = v.w;
    }
    #pragma unroll
    for (int i = t; i < 1024; i += 256) {
        int e  = i >> 4;
        int c4 = (i & 15) << 2;
        *(float4*)&sB[e][c4] = *(const float4*)(S + e * OO + c4);
    }
    __syncthreads();

    const int tr = (t >> 4) << 2;   // row base (0..60)
    const int tc = (t & 15) << 2;   // col base (0..60)
    float acc[4][4];
    #pragma unroll
    for (int i = 0; i < 4; i++)
        #pragma unroll
        for (int j = 0; j < 4; j++) acc[i][j] = 0.f;

    #pragma unroll 8
    for (int e = 0; e < 64; e++) {
        float4 a = *(const float4*)&sA[e][tr];
        float4 b = *(const float4*)&sB[e][tc];
        float av[4] = {a.x, a.y, a.z, a.w};
        float bv[4] = {b.x, b.y, b.z, b.w};
        #pragma unroll
        for (int i = 0; i < 4; i++)
            #pragma unroll
            for (int j = 0; j < 4; j++)
                acc[i][j] = fmaf(av[i], bv[j], acc[i][j]);
    }

    float* outBase = g_priors + (size_t)blockIdx.x * 64 * OO;
    #pragma unroll
    for (int i = 0; i < 4; i++) {
        float4 v = make_float4(acc[i][0], acc[i][1], acc[i][2], acc[i][3]);
        *(float4*)(outBase + (tr + i) * OO + tc) = v;
    }
}

// ---------------------------------------------------------------------------
// One routing iteration (split over N into NSPLIT chunks per b):
//   delta[n,k] = dot(priors[b,n,:], Vacc[b,k,:])        (skipped if FIRST)
//   w[k]       = softmax_k(cc0[b,k,n,o] + delta[n,k])
//   zpart[b,sp,k,o] = sum_{n in chunk} w[k] * priors[b,n,o]
//
// 2 o's per thread (32 o-groups x 8 n-replicas), ~55 regs, 4 blocks/SM.
// ---------------------------------------------------------------------------
template <bool FIRST>
__global__ void __launch_bounds__(256, 4) route_kernel(const float* __restrict__ cc) {
    __shared__ float ps[NCHUNK][68];   // priors chunk; reused as reduction buffer
    __shared__ float ds[NCHUNK][8];    // delta
    __shared__ float vs[KK][68];       // Vacc slice

    const int t  = threadIdx.x;
    const int b  = blockIdx.x >> 3;
    const int sp = blockIdx.x & 7;
    const int n0 = sp * NCHUNK;

    const float* pBase = g_priors + ((size_t)b * NN + n0) * OO;
    #pragma unroll
    for (int i = t; i < NCHUNK * 16; i += 256) {
        int n  = i >> 4;
        int o4 = (i & 15) << 2;
        *(float4*)&ps[n][o4] = *(const float4*)(pBase + n * OO + o4);
    }
    if (!FIRST) {
        if (t < KK * 16) {
            int k  = t >> 4;
            int o4 = (t & 15) << 2;
            *(float4*)&vs[k][o4] = *(const float4*)(g_vacc + ((size_t)b * KK + k) * OO + o4);
        }
    }
    __syncthreads();

    if (!FIRST) {
        // 512 dots of length 64 across 256 threads (2 each)
        #pragma unroll
        for (int id = t; id < NCHUNK * KK; id += 256) {
            int n = id >> 3;
            int k = id & 7;
            float s = 0.f;
            #pragma unroll
            for (int o = 0; o < OO; o++) s = fmaf(ps[n][o], vs[k][o], s);
            ds[n][k] = s;
        }
        __syncthreads();
    }

    const int og   = t & 31;        // o-pair index
    const int ob   = og << 1;
    const int nrep = t >> 5;        // 8 n-replicas (one warp each)
    float acc[KK][2];
    #pragma unroll
    for (int k = 0; k < KK; k++) { acc[k][0] = 0.f; acc[k][1] = 0.f; }

    const float* ccBase = cc + ((size_t)b * KK * NN + n0) * OO + ob;
    const float L2E = 1.4426950408889634f;

    for (int n = nrep; n < NCHUNK; n += 8) {
        float2 p2 = *(const float2*)&ps[n][ob];
        float c[KK][2];
        #pragma unroll
        for (int k = 0; k < KK; k++) {
            float2 c2 = *(const float2*)(ccBase + ((size_t)k * NN + n) * OO);
            c[k][0] = c2.x; c[k][1] = c2.y;
            if (!FIRST) {
                float d = ds[n][k];
                c[k][0] += d; c[k][1] += d;
            }
        }
        float m0 = c[0][0], m1 = c[0][1];
        #pragma unroll
        for (int k = 1; k < KK; k++) {
            m0 = fmaxf(m0, c[k][0]);
            m1 = fmaxf(m1, c[k][1]);
        }
        m0 *= L2E; m1 *= L2E;
        float s0 = 0.f, s1 = 0.f;
        #pragma unroll
        for (int k = 0; k < KK; k++) {
            float e0 = fast_ex2(fmaf(c[k][0], L2E, -m0));
            float e1 = fast_ex2(fmaf(c[k][1], L2E, -m1));
            c[k][0] = e0; c[k][1] = e1;
            s0 += e0; s1 += e1;
        }
        float pr0 = p2.x * fast_rcp(s0);
        float pr1 = p2.y * fast_rcp(s1);
        #pragma unroll
        for (int k = 0; k < KK; k++) {
            acc[k][0] = fmaf(c[k][0], pr0, acc[k][0]);
            acc[k][1] = fmaf(c[k][1], pr1, acc[k][1]);
        }
    }

    __syncthreads();   // done reading ps — reuse as reduction buffer

    // Cross-warp reduction: red[(w*32 + og)*17 + kj], kj = k*2+j, stride 17
    // (coprime with 32 -> conflict-free). 8*32*17 = 4352 floats = ps exactly.
    float* red = &ps[0][0];
    {
        float* dst = red + (size_t)(nrep * 32 + og) * 17;
        #pragma unroll
        for (int k = 0; k < KK; k++) {
            dst[k * 2]     = acc[k][0];
            dst[k * 2 + 1] = acc[k][1];
        }
    }
    __syncthreads();

    #pragma unroll
    for (int id = t; id < 512; id += 256) {
        int og_ = id >> 4;          // 0..31
        int kj  = id & 15;          // 0..15
        float ssum = 0.f;
        #pragma unroll
        for (int w_ = 0; w_ < 8; w_++)
            ssum += red[(size_t)(w_ * 32 + og_) * 17 + kj];
        int k = kj >> 1;
        int j = kj & 1;
        int o = (og_ << 1) + j;
        g_zpart[(((size_t)b * NSPLIT + sp) * KK + k) * OO + o] = ssum;
    }
}

// ---------------------------------------------------------------------------
// Sum partials over splits, squash. MODE 0: Vacc = v (iter 0);
// MODE 1: Vacc += v; MODE 2: write final output.
// One warp per (b,k); 2 o's per lane.
// ---------------------------------------------------------------------------
template <int MODE>
__global__ void __launch_bounds__(256) finish_kernel(float* __restrict__ out) {
    const int gw   = (blockIdx.x << 3) + (threadIdx.x >> 5);   // 0..2047
    const int lane = threadIdx.x & 31;
    const int b = gw >> 3;
    const int k = gw & 7;

    float z0 = 0.f, z1 = 0.f;
    #pragma unroll
    for (int sp = 0; sp < NSPLIT; sp++) {
        const float* zp = g_zpart + (((size_t)b * NSPLIT + sp) * KK + k) * OO;
        z0 += zp[lane];
        z1 += zp[lane + 32];
    }
    float sq = z0 * z0 + z1 * z1;
    #pragma unroll
    for (int off = 16; off; off >>= 1)
        sq += __shfl_xor_sync(0xffffffffu, sq, off);

    float scale = sq / ((1.f + sq) * sqrtf(sq + 1e-9f));
    float v0 = scale * z0;
    float v1 = scale * z1;

    size_t base = ((size_t)b * KK + k) * OO;
    if (MODE == 2) {
        out[base + lane]      = v0;
        out[base + lane + 32] = v1;
    } else if (MODE == 0) {
        g_vacc[base + lane]      = v0;
        g_vacc[base + lane + 32] = v1;
    } else {
        g_vacc[base + lane]      += v0;
        g_vacc[base + lane + 32] += v1;
    }
}

// ---------------------------------------------------------------------------
extern "C" void kernel_launch(void* const* d_in, const int* in_sizes, int n_in,
                              void* d_out, int out_size) {
    const float* emb = (const float*)d_in[0];   // (B, N, E)
    const float* S   = (const float*)d_in[1];   // (E, O)
    const float* cc  = (const float*)d_in[2];   // (B, K, N, O)
    float* out = (float*)d_out;                 // (B, K, O)
    (void)in_sizes; (void)n_in; (void)out_size;

    gemm_kernel<<<BB * NN / 64, 256>>>(emb, S);

    route_kernel<true><<<BB * NSPLIT, 256>>>(cc);
    finish_kernel<0><<<BB * KK / 8, 256>>>(nullptr);

    route_kernel<false><<<BB * NSPLIT, 256>>>(cc);
    finish_kernel<1><<<BB * KK / 8, 256>>>(nullptr);

    route_kernel<false><<<BB * NSPLIT, 256>>>(cc);
    finish_kernel<2><<<BB * KK / 8, 256>>>(out);
}